// round 9
// baseline (speedup 1.0000x reference)
#include <cuda_runtime.h>
#include <math.h>

#define NP     4096
#define TOTAL  65536
#define ROWS   32
#define NB     256
#define LOV    (-5.0f)
#define HIV    (5.0f)
#define WBIN   ((HIV - LOV) / NB)
#define INVW   ((float)NB / (HIV - LOV))
#define PAD    3
#define WMIN   384
#define WCAPP  384                 // window cap in PAIRS (768 points, 12 KB)
#define BT     64
#define QPB    64
#define NBLK   (2 * TOTAL / QPB)   // 2048
#define FULLM  0xFFFFFFFFu

__device__ float4 g_sorted[2 * TOTAL];
__device__ int    g_hist8[ROWS][8][NB];
__device__ int    g_segstart[ROWS][8][NB];
__device__ int    g_binstart[ROWS][NB + 1];
__device__ float  g_partial[NBLK];

__device__ __forceinline__ int binof(float v) {
    int b = (int)((v - LOV) * INVW);
    return min(max(b, 0), NB - 1);
}

#define FMA2(d, a, bb, c) \
    asm("fma.rn.f32x2 %0, %1, %2, %3;" : "=l"(d) : "l"(a), "l"(bb), "l"(c))

__device__ __forceinline__ unsigned long long bcast2(float v) {
    unsigned long long r;
    unsigned u = __float_as_uint(v);
    asm("mov.b64 %0, {%1, %1};" : "=l"(r) : "r"(u));
    return r;
}

__device__ __forceinline__ void minacc2(float& mlo, float& mhi, unsigned long long t) {
    unsigned lo, hi;
    asm("mov.b64 {%0, %1}, %2;" : "=r"(lo), "=r"(hi) : "l"(t));
    mlo = fminf(mlo, __uint_as_float(lo));
    mhi = fminf(mhi, __uint_as_float(hi));
}

__global__ __launch_bounds__(256) void hist_kernel(const float* __restrict__ x,
                                                   const float* __restrict__ y) {
    int row = blockIdx.x >> 3, seg = blockIdx.x & 7;
    const float* src = ((row >= 16) ? y : x) + (size_t)(row & 15) * NP * 3;
    __shared__ int h[NB];
    int tid = threadIdx.x;
    h[tid] = 0;
    __syncthreads();
    int p0 = seg * 512 + tid * 2;
    atomicAdd(&h[binof(src[3 * p0])], 1);
    atomicAdd(&h[binof(src[3 * (p0 + 1)])], 1);
    __syncthreads();
    g_hist8[row][seg][tid] = h[tid];
}

// Per-row: bin totals -> scan -> binstart; then per-seg exclusive starts.
__global__ __launch_bounds__(NB) void prefix_kernel() {
    int row = blockIdx.x, tid = threadIdx.x;
    __shared__ int s[NB];
    int hv[8];
    int v = 0;
    #pragma unroll
    for (int k = 0; k < 8; k++) { hv[k] = g_hist8[row][k][tid]; v += hv[k]; }
    s[tid] = v;
    __syncthreads();
    #pragma unroll
    for (int off = 1; off < NB; off <<= 1) {
        int t = (tid >= off) ? s[tid - off] : 0;
        __syncthreads();
        s[tid] += t;
        __syncthreads();
    }
    int run = s[tid] - v;                 // exclusive binstart
    g_binstart[row][tid] = run;
    if (tid == NB - 1) g_binstart[row][NB] = s[tid];
    #pragma unroll
    for (int k = 0; k < 8; k++) { g_segstart[row][k][tid] = run; run += hv[k]; }
}

// No global atomics: smem-local ranks + per-segment start offsets.
__global__ __launch_bounds__(256) void scatter_kernel(const float* __restrict__ x,
                                                      const float* __restrict__ y) {
    int row = blockIdx.x >> 3, seg = blockIdx.x & 7;
    const float* src = ((row >= 16) ? y : x) + (size_t)(row & 15) * NP * 3;
    __shared__ int cnt[NB];
    int tid = threadIdx.x;
    cnt[tid] = 0;
    __syncthreads();
    int p0 = seg * 512 + tid * 2;
    const float2* s2 = (const float2*)(src + 3 * p0);
    float2 ab = s2[0], ca = s2[1], bc = s2[2];
    float4* dst = g_sorted + (size_t)row * NP;
    {
        int bin = binof(ab.x);
        int pos = g_segstart[row][seg][bin] + atomicAdd(&cnt[bin], 1);
        dst[pos] = make_float4(ab.x, ab.y, ca.x,
                               0.5f * (ab.x * ab.x + ab.y * ab.y + ca.x * ca.x));
    }
    {
        int bin = binof(ca.y);
        int pos = g_segstart[row][seg][bin] + atomicAdd(&cnt[bin], 1);
        dst[pos] = make_float4(ca.y, bc.x, bc.y,
                               0.5f * (ca.y * ca.y + bc.x * bc.x + bc.y * bc.y));
    }
}

__global__ __launch_bounds__(BT) void chamfer_kernel() {
    __shared__ int    sbs[NB + 1];
    __shared__ float4 swin[2 * WCAPP];    // pair layout: {x0x1y0y1}{z0z1w0w1}
    __shared__ float4 qbuf[QPB];
    __shared__ float  sdist[QPB];
    __shared__ int    slist[QPB];
    __shared__ float  smin[QPB];
    __shared__ int    scount;
    __shared__ int    wKL[2], wKR[2];
    __shared__ int    wSkLo[2], wSkHi[2];
    __shared__ int    bWinLo, bWinCnt, bPairs;

    int blk = blockIdx.x;                 // 2048 blocks
    int dir = blk >> 10;
    int b   = (blk >> 6) & 15;
    int qt  = blk & 63;                   // 64 tiles of 64 queries
    int tid = threadIdx.x;
    int lane = tid & 31;
    int wid  = tid >> 5;

    int qRow  = dir ? (16 + b) : b;
    int dbRow = dir ? b : (16 + b);
    const float4* db = g_sorted + (size_t)dbRow * NP;

    for (int k = tid; k <= NB; k += BT) sbs[k] = g_binstart[dbRow][k];
    if (tid == 0) scount = 0;

    float4 q = g_sorted[(size_t)qRow * NP + qt * QPB + tid];
    qbuf[tid] = q;
    __syncthreads();

    // Per-warp window: span + PAD, count-extended to WMIN.
    int myBin = binof(q.x);
    int kL = (int)__reduce_min_sync(FULLM, (unsigned)myBin);
    int kR = (int)__reduce_max_sync(FULLM, (unsigned)myBin);
    kL = max(kL - PAD, 0);
    kR = min(kR + PAD, NB - 1);
    while (sbs[kR + 1] - sbs[kL] < WMIN && (kL > 0 || kR < NB - 1)) {
        if (kL > 0) kL--;
        if (kR < NB - 1) kR++;
    }
    if (lane == 0) { wKL[wid] = kL; wKR[wid] = kR; }
    __syncthreads();

    if (tid == 0) {
        int kLb = min(wKL[0], wKL[1]);
        int kRb = max(wKR[0], wKR[1]);
        int lo  = sbs[kLb];
        int cnt = sbs[kRb + 1] - lo;
        bWinLo  = lo;
        bWinCnt = cnt;
        bPairs  = min((cnt + 1) >> 1, WCAPP);
    }
    __syncthreads();
    int winLo = bWinLo, winCnt = bWinCnt, pairs = bPairs;
    int covEnd = winLo + min(winCnt, 2 * pairs);    // absolute coverage end

    // Stage pairs (duplicate last point for odd/overflow tails).
    for (int k = tid; k < pairs; k += BT) {
        int i0 = winLo + 2 * k;
        int i1 = min(i0 + 1, covEnd - 1);
        float4 p0 = db[i0];
        float4 p1 = db[i1];
        swin[2 * k]     = make_float4(p0.x, p1.x, p0.y, p1.y);
        swin[2 * k + 1] = make_float4(p0.z, p1.z, p0.w, p1.w);
    }

    // Warp sub-range in pairs (floor/ceil rounding -> superset of warp window).
    int pLo = max((sbs[kL] - winLo) >> 1, 0);
    int pHi = min((sbs[kR + 1] - winLo + 1) >> 1, pairs);
    bool clampedL = (sbs[kL] < winLo);
    bool clampedR = (sbs[kR + 1] > covEnd);
    if (lane == 0) {
        wSkLo[wid] = winLo + 2 * pLo;
        wSkHi[wid] = min(winLo + 2 * pHi, covEnd);
    }
    __syncthreads();

    unsigned long long nqx = bcast2(-q.x), nqy = bcast2(-q.y), nqz = bcast2(-q.z);
    float m0 = 1e30f, m1 = 1e30f, m2 = 1e30f, m3 = 1e30f;

    const ulonglong2* sp = (const ulonglong2*)swin;
    int k = pLo;
    for (; k + 2 <= pHi; k += 2) {
        ulonglong2 A0 = sp[2 * k];
        ulonglong2 B0 = sp[2 * k + 1];
        ulonglong2 A1 = sp[2 * k + 2];
        ulonglong2 B1 = sp[2 * k + 3];
        unsigned long long t0, t1;
        FMA2(t0, B0.x, nqz, B0.y);
        FMA2(t0, A0.y, nqy, t0);
        FMA2(t0, A0.x, nqx, t0);
        FMA2(t1, B1.x, nqz, B1.y);
        FMA2(t1, A1.y, nqy, t1);
        FMA2(t1, A1.x, nqx, t1);
        minacc2(m0, m1, t0);
        minacc2(m2, m3, t1);
    }
    for (; k < pHi; ++k) {
        ulonglong2 A0 = sp[2 * k];
        ulonglong2 B0 = sp[2 * k + 1];
        unsigned long long t0;
        FMA2(t0, B0.x, nqz, B0.y);
        FMA2(t0, A0.y, nqy, t0);
        FMA2(t0, A0.x, nqx, t0);
        minacc2(m0, m1, t0);
    }
    float m = fminf(fminf(m0, m1), fminf(m2, m3));

    // Exact per-lane exclusion bound at warp-window bin edges.
    float thr   = q.w + m;
    float edgeL = LOV + (float)kL * WBIN;
    float edgeR = LOV + (float)(kR + 1) * WBIN;
    float gl = fmaxf(q.x - edgeL, 0.0f);
    float gr = fmaxf(edgeR - q.x, 0.0f);
    bool dL = !clampedL && ((kL == 0)      || (0.5f * gl * gl >= thr));
    bool dR = !clampedR && ((kR == NB - 1) || (0.5f * gr * gr >= thr));

    sdist[tid] = sqrtf(1e-6f + fmaxf(2.0f * thr, 0.0f));

    bool need = !(dL && dR);
    unsigned mk = __ballot_sync(FULLM, need);
    int nneed = __popc(mk);
    if (nneed) {
        int base = 0;
        if (lane == 0) base = atomicAdd(&scount, nneed);
        base = __shfl_sync(FULLM, base, 0);
        if (need) {
            int rank = __popc(mk & ((1u << lane) - 1));
            slist[base + rank] = tid;
            smin[base + rank] = m;
        }
    }
    __syncthreads();

    // Block-local exact phase 2: one warp per spilled query, skip scanned range.
    int ns = scount;
    for (int i = wid; i < ns; i += BT / 32) {
        int t = slist[i];
        float mm = smin[i];
        float4 q2 = qbuf[t];
        int w2 = t >> 5;
        int skLo = wSkLo[w2], skHi = wSkHi[w2];

        float d1 = sqrtf(fmaxf(2.0f * (q2.w + mm), 0.0f)) * 1.0005f + 1e-5f;
        int lo2 = sbs[binof(q2.x - d1)];
        int hi2 = sbs[binof(q2.x + d1) + 1];

        int hA = min(hi2, skLo);
        for (int jj = lo2 + lane; jj < hA; jj += 32) {
            float4 p = __ldg(&db[jj]);
            mm = fminf(mm, fmaf(-q2.x, p.x, fmaf(-q2.y, p.y, fmaf(-q2.z, p.z, p.w))));
        }
        int lB = max(lo2, skHi);
        for (int jj = lB + lane; jj < hi2; jj += 32) {
            float4 p = __ldg(&db[jj]);
            mm = fminf(mm, fmaf(-q2.x, p.x, fmaf(-q2.y, p.y, fmaf(-q2.z, p.z, p.w))));
        }
        #pragma unroll
        for (int o = 16; o; o >>= 1)
            mm = fminf(mm, __shfl_xor_sync(FULLM, mm, o));
        if (lane == 0)
            sdist[t] = sqrtf(1e-6f + fmaxf(2.0f * (q2.w + mm), 0.0f));
    }
    __syncthreads();

    // Deterministic fixed-tree reduction (64 values).
    #pragma unroll
    for (int st = BT / 2; st > 0; st >>= 1) {
        if (tid < st) sdist[tid] += sdist[tid + st];
        __syncthreads();
    }
    if (tid == 0) g_partial[blk] = sdist[0];
}

__global__ __launch_bounds__(512) void finalize_kernel(float* __restrict__ out) {
    __shared__ float s[512];
    int tid = threadIdx.x;
    float v = 0.0f;
    #pragma unroll
    for (int i = 0; i < 4; i++) v += g_partial[tid + 512 * i];
    s[tid] = v;
    __syncthreads();
    #pragma unroll
    for (int st = 256; st > 0; st >>= 1) {
        if (tid < st) s[tid] += s[tid + st];
        __syncthreads();
    }
    if (tid == 0) out[0] = s[0] * (1.0f / (float)TOTAL);
}

extern "C" void kernel_launch(void* const* d_in, const int* in_sizes, int n_in,
                              void* d_out, int out_size) {
    const float* x = (const float*)d_in[0];
    const float* y = (const float*)d_in[1];
    float* out = (float*)d_out;

    hist_kernel<<<256, 256>>>(x, y);
    prefix_kernel<<<ROWS, NB>>>();
    scatter_kernel<<<256, 256>>>(x, y);
    chamfer_kernel<<<NBLK, BT>>>();
    finalize_kernel<<<1, 512>>>(out);
}